// round 13
// baseline (speedup 1.0000x reference)
#include <cuda_runtime.h>
#include <cuda_fp16.h>
#include <mma.h>
#include <cstdint>

using namespace nvcuda;

#define DIM_IN  128
#define DIM_HID 256
#define DIM_OUT 128
#define NEXP    8
#define MAXN    65536
#define MAXROWS (2 * MAXN)
#define TM      64
#define MAXTILES (MAXROWS / TM + NEXP)

// ---------------- device scratch ----------------
__device__ int    g_counts[NEXP];
__device__ int    g_cursor[NEXP];
__device__ int    g_numTiles;
__device__ int    g_tileExpert[MAXTILES];
__device__ int    g_tileStart[MAXTILES];
__device__ int    g_tileRows[MAXTILES];
__device__ int    g_tokE[MAXN];
__device__ float2 g_tokW[MAXN];
__device__ int    g_rowToken[MAXROWS];
__device__ float  g_rowW[MAXROWS];

__device__ __align__(16) __half g_xf[MAXN * DIM_IN];
__device__ __align__(16) __half g_w1f[NEXP * DIM_IN * DIM_HID];  // [e][k=128][n=256]
__device__ __align__(16) __half g_w2f[NEXP * DIM_HID * DIM_OUT]; // [e][k=256][n=128]

__device__ __forceinline__ uint32_t packh2(float a, float b) {
    __half2 h = __floats2half2_rn(a, b);
    return *reinterpret_cast<uint32_t*>(&h);
}

// ---------------- kernel: weight fp16 convert + zero counts ----------------
__global__ void __launch_bounds__(256) moe_prep(
    const float* __restrict__ W1, const float* __restrict__ W2)
{
    int idx = blockIdx.x * 256 + threadIdx.x;          // 0 .. 65535
    if (blockIdx.x == 0 && threadIdx.x < NEXP) g_counts[threadIdx.x] = 0;
    if (idx < 65536) {
        float4 v = reinterpret_cast<const float4*>(W1)[idx];
        reinterpret_cast<uint2*>(g_w1f)[idx] = make_uint2(packh2(v.x, v.y), packh2(v.z, v.w));
        float4 w = reinterpret_cast<const float4*>(W2)[idx];
        reinterpret_cast<uint2*>(g_w2f)[idx] = make_uint2(packh2(w.x, w.y), packh2(w.z, w.w));
    }
}

// ---------------- kernel: gate (+ X fp16 + output zeroing) ----------------
__global__ void __launch_bounds__(256) moe_gate(
    const float* __restrict__ x, const float* __restrict__ Wp,
    const float* __restrict__ bp, const float* __restrict__ Ee,
    float* __restrict__ outbuf, long zero_lo, long zero_hi,
    float* __restrict__ pout, int n)
{
    __shared__ float WpS[DIM_IN * 64];
    __shared__ float EeS[64 * NEXP];
    __shared__ float hS[8][64];
    __shared__ float pS[8][8];
    __shared__ int   cntS[NEXP];

    int tid = threadIdx.x, warp = tid >> 5, lane = tid & 31;
    for (int i = tid; i < DIM_IN * 64; i += 256) WpS[i] = Wp[i];
    for (int i = tid; i < 64 * NEXP; i += 256)   EeS[i] = Ee[i];
    if (tid < NEXP) cntS[tid] = 0;
    if (blockIdx.x == 0 && tid == 0) {
        for (long i = zero_lo; i < zero_hi; i++) outbuf[i] = 0.f;
    }
    __syncthreads();

    const float4 z4 = make_float4(0.f, 0.f, 0.f, 0.f);

    for (int tok = blockIdx.x * 8 + warp; tok < n; tok += gridDim.x * 8) {
        float xr[4];
        #pragma unroll
        for (int i = 0; i < 4; i++) xr[i] = x[(long)tok * DIM_IN + lane + 32 * i];

        reinterpret_cast<float4*>(outbuf + (long)tok * DIM_OUT)[lane] = z4;

        #pragma unroll
        for (int i = 0; i < 4; i++)
            g_xf[(long)tok * DIM_IN + lane + 32 * i] = __float2half_rn(xr[i]);

        float h0 = bp[lane], h1 = bp[lane + 32];
        #pragma unroll
        for (int d = 0; d < DIM_IN; d++) {
            float xd = __shfl_sync(0xffffffffu, xr[d >> 5], d & 31);
            h0 += xd * WpS[d * 64 + lane];
            h1 += xd * WpS[d * 64 + lane + 32];
        }
        hS[warp][lane] = h0;
        hS[warp][lane + 32] = h1;
        __syncwarp();

        if (lane < NEXP) {
            float lg = 0.f;
            #pragma unroll
            for (int e2 = 0; e2 < 64; e2++) lg += hS[warp][e2] * EeS[e2 * NEXP + lane];
            float p = 1.f / (1.f + expf(-lg * 0.2f));   // tau = 5
            pS[warp][lane] = p;
            if (pout) pout[(long)tok * NEXP + lane] = p;
        }
        __syncwarp();

        if (lane == 0) {
            float v0 = -1.f, v1 = -1.f; int i0 = 0, i1 = 0;
            #pragma unroll
            for (int j = 0; j < NEXP; j++) {
                float pv = pS[warp][j];
                if (pv > v0) { v1 = v0; i1 = i0; v0 = pv; i0 = j; }
                else if (pv > v1) { v1 = pv; i1 = j; }
            }
            float s = v0 + v1 + 1e-10f;
            g_tokE[tok] = i0 | (i1 << 8);
            g_tokW[tok] = make_float2(v0 / s, v1 / s);
            atomicAdd(&cntS[i0], 1);
            atomicAdd(&cntS[i1], 1);
        }
        __syncwarp();
    }
    __syncthreads();
    if (tid < NEXP) atomicAdd(&g_counts[tid], cntS[tid]);
}

// ---------------- kernel: scan + tile map (64-row tiles) ----------------
__global__ void moe_build() {
    if (threadIdx.x == 0) {
        int off = 0, tile = 0;
        for (int e = 0; e < NEXP; e++) {
            int c = g_counts[e];
            g_cursor[e] = off;
            for (int t = 0; t < c && tile < MAXTILES; t += TM) {
                g_tileExpert[tile] = e;
                g_tileStart[tile]  = off + t;
                g_tileRows[tile]   = min(TM, c - t);
                tile++;
            }
            off += c;
        }
        g_numTiles = tile;
    }
}

// ---------------- kernel: scatter ----------------
__global__ void __launch_bounds__(256) moe_scatter(int n) {
    __shared__ int cnt[NEXP];
    __shared__ int base[NEXP];
    int tid = threadIdx.x;
    if (tid < NEXP) cnt[tid] = 0;
    __syncthreads();

    int tok = blockIdx.x * 256 + tid;
    int e0 = 0, e1 = 0, r0 = 0, r1 = 0; float2 w = make_float2(0.f, 0.f);
    bool ok = (tok < n);
    if (ok) {
        int e01 = g_tokE[tok];
        w = g_tokW[tok];
        e0 = e01 & 255; e1 = (e01 >> 8) & 255;
        r0 = atomicAdd(&cnt[e0], 1);
        r1 = atomicAdd(&cnt[e1], 1);
    }
    __syncthreads();
    if (tid < NEXP) base[tid] = atomicAdd(&g_cursor[tid], cnt[tid]);
    __syncthreads();
    if (ok) {
        int p0 = base[e0] + r0; g_rowToken[p0] = tok; g_rowW[p0] = w.x;
        int p1 = base[e1] + r1; g_rowToken[p1] = tok; g_rowW[p1] = w.y;
    }
}

// ---------------- kernel: expert GEMM (fp16, 64-row tiles, 2 CTAs/SM) ----------------
using FragA = wmma::fragment<wmma::matrix_a, 16, 16, 16, __half, wmma::row_major>;
using FragB = wmma::fragment<wmma::matrix_b, 16, 16, 16, __half, wmma::row_major>;
using FragC = wmma::fragment<wmma::accumulator, 16, 16, 16, float>;

#define LDX 136           // X / W2-chunk plane: 64 x 136 half
#define LDW 264           // W1 / H plane:       128 x 264 half
#define XB  (TM * LDX * 2)     // 17408 B
#define WB  (128 * LDW * 2)    // 67584 B
#define SMEM_EXP (XB + WB)     // 84992 B  -> 2 CTAs/SM
#define NTHR 256

__global__ void __launch_bounds__(NTHR, 2) moe_expert(
    const float* __restrict__ b1, const float* __restrict__ b2,
    float* __restrict__ out)
{
    int tile = blockIdx.x;
    if (tile >= g_numTiles) return;
    int e        = g_tileExpert[tile];
    int rowStart = g_tileStart[tile];
    int nRows    = g_tileRows[tile];

    extern __shared__ __align__(16) unsigned char sm[];
    __half* xr = (__half*)sm;                 // 64 x LDX (X, later W2 k-chunks of 64)
    __half* hw = (__half*)(sm + XB);          // 128 x LDW (W1, later H in rows 0..63)
    float* stage = (float*)sm;                // 64 x 68 fp32 = 17408 B over xr
    float* stC   = (float*)hw;                // 64 x 132 fp32 = 33792 B over hw

    __shared__ int   tokS[TM];
    __shared__ float wS[TM];
    __shared__ float b1s[256];
    __shared__ float b2s[128];

    int tid = threadIdx.x, warp = tid >> 5;
    int wm = warp >> 1, wn = warp & 1;        // 4 x 2 warp grid
    int m0 = wm * 16;

    if (tid < TM) {
        int tok = -1; float w = 0.f;
        if (tid < nRows) { tok = g_rowToken[rowStart + tid]; w = g_rowW[rowStart + tid]; }
        tokS[tid] = tok; wS[tid] = w;
    }
    b1s[tid] = b1[(long)e * DIM_HID + tid];
    if (tid < 128) b2s[tid] = b2[(long)e * DIM_OUT + tid];
    __syncthreads();

    // ---- fill X (gathered fp16, 64 rows) ----
    const uint4* x4 = (const uint4*)g_xf;
    #pragma unroll 2
    for (int i = tid; i < TM * 16; i += NTHR) {
        int r = i >> 4, u = i & 15;
        uint4 v = make_uint4(0, 0, 0, 0);
        int tok = tokS[r];
        if (tok >= 0) v = x4[(long)tok * 16 + u];
        *reinterpret_cast<uint4*>(&xr[r * LDX + u * 8]) = v;
    }
    // ---- fill W1 [k=128][n=256] ----
    const uint4* w14 = (const uint4*)(g_w1f + (long)e * DIM_IN * DIM_HID);
    #pragma unroll 4
    for (int i = tid; i < 128 * 32; i += NTHR) {
        int r = i >> 5, u = i & 31;
        *reinterpret_cast<uint4*>(&hw[r * LDW + u * 8]) = w14[i];
    }
    __syncthreads();

    // ---- GEMM1: Hraw[64x256] = X @ W1 ; warp tile 16 x 128 ----
    FragC acc[8];
    #pragma unroll
    for (int nt = 0; nt < 8; nt++) wmma::fill_fragment(acc[nt], 0.f);

    int nbase = wn * 128;
    #pragma unroll
    for (int ks = 0; ks < 8; ks++) {
        FragA a;
        wmma::load_matrix_sync(a, &xr[m0 * LDX + ks * 16], LDX);
        #pragma unroll
        for (int nt = 0; nt < 8; nt++) {
            FragB b;
            wmma::load_matrix_sync(b, &hw[(ks * 16) * LDW + nbase + nt * 16], LDW);
            wmma::mma_sync(acc[nt], a, b, acc[nt]);
        }
    }
    __syncthreads();   // X and W1 fully consumed

    // ---- H = relu(acc + b1): 4 phases of 64 cols through dead X region ----
    // H lives in hw rows 0..63 (over consumed W1 rows)
    #pragma unroll
    for (int p = 0; p < 4; p++) {
        if (wn == (p >> 1)) {
            #pragma unroll
            for (int j = 0; j < 4; j++)
                wmma::store_matrix_sync(&stage[m0 * 68 + j * 16],
                                        acc[(p & 1) * 4 + j], 68, wmma::mem_row_major);
        }
        __syncthreads();
        #pragma unroll 2
        for (int i = tid; i < TM * 64; i += NTHR) {
            int r = i >> 6, c = i & 63;
            float v = stage[r * 68 + c] + b1s[p * 64 + c];
            v = v > 0.f ? v : 0.f;
            hw[r * LDW + p * 64 + c] = __float2half_rn(v);
        }
        __syncthreads();
    }

    // ---- GEMM2: C[64x128] = H @ W2 ; 4 K-chunks of 64 through X region ----
    FragC acc2[4];
    #pragma unroll
    for (int nt = 0; nt < 4; nt++) wmma::fill_fragment(acc2[nt], 0.f);

    const uint4* w24 = (const uint4*)(g_w2f + (long)e * DIM_HID * DIM_OUT);
    #pragma unroll
    for (int ch = 0; ch < 4; ch++) {
        #pragma unroll 2
        for (int i = tid; i < 64 * 16; i += NTHR) {      // 64 k-rows x 128 n
            int r = i >> 4, u = i & 15;
            *reinterpret_cast<uint4*>(&xr[r * LDX + u * 8]) = w24[(ch * 64 + r) * 16 + u];
        }
        __syncthreads();
        #pragma unroll
        for (int ks = 0; ks < 4; ks++) {
            FragA a;
            wmma::load_matrix_sync(a, &hw[m0 * LDW + ch * 64 + ks * 16], LDW);
            #pragma unroll
            for (int nt = 0; nt < 4; nt++) {
                FragB b;
                wmma::load_matrix_sync(b, &xr[(ks * 16) * LDX + wn * 64 + nt * 16], LDX);
                wmma::mma_sync(acc2[nt], a, b, acc2[nt]);
            }
        }
        __syncthreads();
    }

    // ---- epilogue: stage C over dead H region, weighted atomics ----
    #pragma unroll
    for (int nt = 0; nt < 4; nt++)
        wmma::store_matrix_sync(&stC[m0 * 132 + wn * 64 + nt * 16],
                                acc2[nt], 132, wmma::mem_row_major);
    __syncthreads();

    #pragma unroll 2
    for (int i = tid; i < TM * DIM_OUT; i += NTHR) {
        int r = i >> 7, c = i & 127;
        int tok = tokS[r];
        if (tok >= 0)
            atomicAdd(&out[(long)tok * DIM_OUT + c],
                      wS[r] * (stC[r * 132 + c] + b2s[c]));
    }
}

// ---------------- launch ----------------
extern "C" void kernel_launch(void* const* d_in, const int* in_sizes, int n_in,
                              void* d_out, int out_size) {
    const float* x  = (const float*)d_in[0];
    const float* Wp = (const float*)d_in[1];
    const float* bp = (const float*)d_in[2];
    const float* Ee = (const float*)d_in[3];
    const float* W1 = (const float*)d_in[4];
    const float* b1 = (const float*)d_in[5];
    const float* W2 = (const float*)d_in[6];
    const float* b2 = (const float*)d_in[7];
    float* out = (float*)d_out;

    int n = in_sizes[0] / DIM_IN;

    float* pout = nullptr;
    long need = (long)n * DIM_OUT + (long)n * NEXP;
    long zlo = (long)n * DIM_OUT, zhi = (long)out_size;
    if ((long)out_size >= need) {
        pout = out + ((long)out_size - (long)n * NEXP);
        zhi = (long)out_size - (long)n * NEXP;
    }

    moe_prep<<<256, 256>>>(W1, W2);
    moe_gate<<<1024, 256>>>(x, Wp, bp, Ee, out, zlo, zhi, pout, n);
    moe_build<<<1, 1>>>();
    moe_scatter<<<(n + 255) / 256, 256>>>(n);

    int tiles = (2 * n + TM - 1) / TM + NEXP;
    cudaFuncSetAttribute(moe_expert, cudaFuncAttributeMaxDynamicSharedMemorySize, SMEM_EXP);
    moe_expert<<<tiles, NTHR, SMEM_EXP>>>(b1, b2, out);
}